// round 17
// baseline (speedup 1.0000x reference)
#include <cuda_runtime.h>
#include <cuda_fp16.h>
#include <cstdint>

// Conv2d 3x3 s1 p1, NCHW, implicit GEMM on mma.sync.
// fp16 hi/lo split on A (input), fp16-truncated B (weights), 2 passes:
//   (Ahi*Bhi) + (Alo*Bhi) = x * w_hi
// Split-N: each CTA does 112 spatial x 64 out-channels -> 63KB smem, 3 CTAs/SM.
// x: [32,64,112,112] f32  w: [128,64,3,3] f32  bias: [128] f32
// out: [32,128,112,112] f32

#define Nn 32
#define Cc 64
#define Kk 128
#define Hh 112
#define Ww 112

// ---------------- smem layout (dynamic) ----------------
// B tile: [64][200] fp16, row stride 400B
#define BSTR   400
#define BTILE  25600
#define SMB    0
// A segs: 2 halves (hi,lo) x [130 rows][72 fp16], row stride 144B
#define XSTR   72
#define XSEG   18720
#define SMX    25600
#define SMEM_TOTAL 63040
// epilogue staging aliases smem base: [j][65] f32 (29.1 KB)

// Pre-packed weights (hi only): [ry][n][200] fp16 (k = dx*64+c, cols 192..199 zero)
__device__ __align__(16) __half g_wpack[3 * 128 * 200];

// Pre-packed input: [half][n][h][w][72] fp16, row stride 144B (cols 64..71 zero).
#define XHALF ((size_t)Nn * Hh * Ww * 72)
__device__ __align__(16) __half g_xpack[2 * XHALF];

// ---------------- helpers ----------------
__device__ __forceinline__ uint32_t smem_u32(const void* p) {
    uint32_t a;
    asm("{ .reg .u64 t; cvta.to.shared.u64 t, %1; cvt.u32.u64 %0, t; }" : "=r"(a) : "l"(p));
    return a;
}
__device__ __forceinline__ void cp16(uint32_t dst, const void* src) {
    asm volatile("cp.async.cg.shared.global [%0], [%1], 16;" :: "r"(dst), "l"(src) : "memory");
}
#define CP_COMMIT() asm volatile("cp.async.commit_group;" ::: "memory")
#define CP_WAIT0()  asm volatile("cp.async.wait_group 0;" ::: "memory")

#define LDSM4(r0, r1, r2, r3, addr) \
    asm volatile("ldmatrix.sync.aligned.m8n8.x4.shared.b16 {%0,%1,%2,%3}, [%4];" \
        : "=r"(r0), "=r"(r1), "=r"(r2), "=r"(r3) : "r"(addr))

#define MMA16816(d, a, b) \
    asm volatile("mma.sync.aligned.m16n8k16.row.col.f32.f16.f16.f32 " \
        "{%0,%1,%2,%3}, {%4,%5,%6,%7}, {%8,%9}, {%0,%1,%2,%3};" \
        : "+f"((d)[0]), "+f"((d)[1]), "+f"((d)[2]), "+f"((d)[3]) \
        : "r"((a)[0]), "r"((a)[1]), "r"((a)[2]), "r"((a)[3]), \
          "r"((b)[0]), "r"((b)[1]))

// ---------------- weight packer ----------------
__global__ void pack_weights_kernel(const float* __restrict__ wgt) {
    int i = blockIdx.x * 256 + threadIdx.x;
    if (i >= 3 * 128 * 200) return;
    int k  = i % 200;
    int t  = i / 200;
    int nK = t % 128;
    int ry = t / 128;
    __half v_out = __float2half(0.0f);
    if (k < 192) {
        int dx = k >> 6, c = k & 63;
        v_out = __float2half(wgt[((nK * Cc + c) * 3 + ry) * 3 + dx]);
    }
    g_wpack[i] = v_out;
}

// ---------------- input packer: x -> fp16 hi/lo smem-image ----------------
__global__ __launch_bounds__(256)
void pack_x_kernel(const float* __restrict__ x) {
    __shared__ float tile[Cc * Ww];            // [c][w], 28.7 KB
    const int h = blockIdx.x;
    const int n = blockIdx.y;
    const int tid = threadIdx.x;

    for (int i = tid; i < Cc * Ww; i += 256) {
        int c = i / Ww, w = i % Ww;
        tile[i] = x[(((size_t)n * Cc + c) * Hh + h) * Ww + w];
    }
    __syncthreads();

    __half* dst = g_xpack + ((size_t)n * Hh + h) * (Ww * 72);
    for (int i = tid; i < Ww * 72; i += 256) {
        int w = i / 72, c = i % 72;
        float v = (c < Cc) ? tile[c * Ww + w] : 0.0f;
        __half hi = __float2half(v);
        __half lo = __float2half(v - __half2float(hi));
        dst[i]         = hi;
        dst[XHALF + i] = lo;
    }
}

// ---------------- one GEMM pass over the 192-wide K chunk ----------------
// Warp tile: 64 (M) x 16 (N). acc[mt 0..3][nt 0..1][4]
__device__ __forceinline__ void mma_pass(uint32_t xbase, uint32_t bbase,
                                         int warp_m, int warp_n, int lane,
                                         float (*acc)[2][4])
{
    #pragma unroll
    for (int s = 0; s < 12; ++s) {
        const int dx = s >> 2;
        const int c0 = (s & 3) * 16;

        uint32_t afr[4][4];
        #pragma unroll
        for (int mt = 0; mt < 4; ++mt) {
            int row = warp_m * 64 + mt * 16 + (lane & 15) + dx;
            uint32_t addr = xbase +
                (uint32_t)(row * XSTR + c0 + ((lane >> 4) << 3)) * 2;
            LDSM4(afr[mt][0], afr[mt][1], afr[mt][2], afr[mt][3], addr);
        }
        uint32_t bfr[2][2];
        {
            int nrow = warp_n * 16 + (lane & 7) + ((lane >> 4) << 3);
            int kk   = s * 16 + (((lane >> 3) & 1) << 3);
            uint32_t addr = bbase + (uint32_t)nrow * BSTR + (uint32_t)kk * 2;
            uint32_t r0, r1, r2, r3;
            LDSM4(r0, r1, r2, r3, addr);
            bfr[0][0] = r0; bfr[0][1] = r1;
            bfr[1][0] = r2; bfr[1][1] = r3;
        }
        #pragma unroll
        for (int mt = 0; mt < 4; ++mt)
            #pragma unroll
            for (int nt = 0; nt < 2; ++nt)
                MMA16816(acc[mt][nt], afr[mt], bfr[nt]);
    }
}

// ---------------- conv kernel ----------------
__global__ __launch_bounds__(256, 3)
void conv_mma_kernel(const float* __restrict__ bias,
                     float* __restrict__ out)
{
    extern __shared__ __align__(16) unsigned char smem[];
    const uint32_t sb = smem_u32(smem);
    const int tid  = threadIdx.x;
    const int lane = tid & 31;
    const int wid  = tid >> 5;
    const int warp_m = wid >> 2;   // 0..1
    const int warp_n = wid & 3;    // 0..3
    const int h  = blockIdx.x;
    const int n  = blockIdx.y;
    const int kh = blockIdx.z;     // 0..1 (out-channel half)

    // zero A pad rows (rows 0, 113..129) in both segs, full 72-col width
    {
        uint32_t* xw = (uint32_t*)(smem + SMX);
        for (int i = tid; i < 2 * 18 * 36; i += 256) {
            int seg = i / (18 * 36);
            int r   = (i / 36) % 18;
            int w   = i % 36;
            int row = (r == 0) ? 0 : (112 + r);     // 0, 113..129
            xw[seg * (XSEG / 4) + row * 36 + w] = 0u;
        }
    }

    float acc[4][2][4];
    #pragma unroll
    for (int a = 0; a < 4; ++a)
        #pragma unroll
        for (int b = 0; b < 2; ++b)
            #pragma unroll
            for (int c = 0; c < 4; ++c) acc[a][b][c] = 0.0f;

    const uint32_t xhi = sb + SMX;
    const uint32_t xlo = sb + SMX + XSEG;
    const uint32_t bb  = sb + SMB;

    #pragma unroll 1
    for (int ry = 0; ry < 3; ++ry) {
        const int hr = h + ry - 1;
        if (hr < 0 || hr >= Hh) continue;       // uniform across block

        __syncthreads();   // prior ry's passes done: B and A reusable

        // async-load B tile for this (ry, kh): 64 rows x 400B = 25.6 KB
        {
            const unsigned char* gsrc =
                (const unsigned char*)&g_wpack[(size_t)(ry * 128 + kh * 64) * 200];
            for (uint32_t off = (uint32_t)tid * 16; off < BTILE; off += 256 * 16)
                cp16(bb + off, gsrc + off);
        }
        // async-load A rows jj=1..112 for both halves (16128 B each, contiguous)
        {
            const unsigned char* a0 =
                (const unsigned char*)(g_xpack + ((size_t)n * Hh + hr) * (Ww * 72));
            const unsigned char* a1 = a0 + XHALF * 2;   // bytes
            for (uint32_t off = (uint32_t)tid * 16; off < 16128u; off += 256 * 16) {
                cp16(xhi + 144 + off, a0 + off);
                cp16(xlo + 144 + off, a1 + off);
            }
        }
        CP_COMMIT();
        CP_WAIT0();
        __syncthreads();

        // 2 passes: (Ahi,Bhi), (Alo,Bhi)  ==  x * w_hi
        mma_pass(xhi, bb, warp_m, warp_n, lane, acc);
        mma_pass(xlo, bb, warp_m, warp_n, lane, acc);
    }

    // ---- epilogue: transpose via smem, coalesced output ----
    __syncthreads();                  // all mma done; alias smem as staging
    float* s_o = (float*)(smem);      // [j][65] f32, 29.1 KB
    #pragma unroll
    for (int mt = 0; mt < 4; ++mt) {
        int j0 = warp_m * 64 + mt * 16 + (lane >> 2);
        #pragma unroll
        for (int nt = 0; nt < 2; ++nt) {
            int k = warp_n * 16 + nt * 8 + ((lane & 3) << 1);
            if (j0 < Ww) {
                s_o[j0 * 65 + k]     = acc[mt][nt][0];
                s_o[j0 * 65 + k + 1] = acc[mt][nt][1];
            }
            if (j0 + 8 < Ww) {
                s_o[(j0 + 8) * 65 + k]     = acc[mt][nt][2];
                s_o[(j0 + 8) * 65 + k + 1] = acc[mt][nt][3];
            }
        }
    }
    __syncthreads();
    const float* bp = bias + kh * 64;
    float* obase = out + (((size_t)n * Kk + kh * 64) * Hh + h) * Ww;
    for (int i = tid; i < 64 * Ww; i += 256) {
        int k = i / Ww, j = i % Ww;
        obase[(size_t)k * Hh * Ww + j] = s_o[j * 65 + k] + bp[k];
    }
}

extern "C" void kernel_launch(void* const* d_in, const int* in_sizes, int n_in,
                              void* d_out, int out_size)
{
    const float* x    = (const float*)d_in[0];
    const float* wgt  = (const float*)d_in[1];
    const float* bias = (const float*)d_in[2];
    float* out = (float*)d_out;

    pack_weights_kernel<<<(3 * 128 * 200 + 255) / 256, 256>>>(wgt);

    dim3 pgrid(Hh, Nn);
    pack_x_kernel<<<pgrid, 256>>>(x);

    cudaFuncSetAttribute(conv_mma_kernel,
                         cudaFuncAttributeMaxDynamicSharedMemorySize, SMEM_TOTAL);

    dim3 grid(Hh, Nn, 2);    // (112, 32, 2) = 7168 CTAs
    conv_mma_kernel<<<grid, 256, SMEM_TOTAL>>>(bias, out);
}